// round 16
// baseline (speedup 1.0000x reference)
#include <cuda_runtime.h>
#include <cuda_bf16.h>
#include <cstdint>

#define HD 128
#define MAXN 40000
#define MAXR 8
#define MAXE 640000
#define MAXNR (MAXN * MAXR)
#define MPADC (((MAXN + 127) / 128) * 128)

/* ---------------- scratch (static device globals; no allocation) ------------- */
__device__ float g_w[MAXR * HD * HD];
__device__ float g_h[(size_t)MPADC * HD];
__device__ int   g_deg2[MAXNR];
__device__ int   g_rsx[MAXNR + 1];
__device__ int   g_cur2[MAXNR];
__device__ int   g_csrc[MAXE];
__device__ int   g_bsum[512], g_boff[512];
__device__ unsigned short g_shi[(size_t)9 * MPADC * HD];
__device__ unsigned short g_slo[(size_t)9 * MPADC * HD];
__device__ unsigned short g_a2hi[(size_t)2 * MPADC * HD];
__device__ unsigned short g_a2lo[(size_t)2 * MPADC * HD];
#define BPITCH 136
#define BTILE  (128 * BPITCH)
__device__ unsigned short g_bimg[11 * 2 * BTILE];

/* ---------------- helpers ---------------------------------------------------- */
__device__ __forceinline__ uint32_t smem_u32(const void* p) {
    uint32_t a;
    asm("{ .reg .u64 t; cvta.to.shared.u64 t, %1; cvt.u32.u64 %0, t; }" : "=r"(a) : "l"(p));
    return a;
}
__device__ __forceinline__ void bsplit(float v, unsigned short& h, unsigned short& l) {
    __nv_bfloat16 bh = __float2bfloat16(v);
    h = __bfloat16_as_ushort(bh);
    l = __bfloat16_as_ushort(__float2bfloat16(v - __bfloat162float(bh)));
}
__device__ __forceinline__ uint32_t pack2(unsigned short a, unsigned short b) {
    return (uint32_t)a | ((uint32_t)b << 16);
}
__device__ __forceinline__ void split_store(float4 v, unsigned short* hi,
                                            unsigned short* lo, size_t idx) {
    unsigned short h0, l0, h1, l1, h2, l2, h3, l3;
    bsplit(v.x, h0, l0); bsplit(v.y, h1, l1);
    bsplit(v.z, h2, l2); bsplit(v.w, h3, l3);
    *(uint2*)&hi[idx] = make_uint2(pack2(h0, h1), pack2(h2, h3));
    *(uint2*)&lo[idx] = make_uint2(pack2(l0, l1), pack2(l2, l3));
}

#define LDSM4(r, addr)                                                             \
    asm volatile("ldmatrix.sync.aligned.m8n8.x4.shared.b16 {%0,%1,%2,%3}, [%4];"   \
        : "=r"((r)[0]), "=r"((r)[1]), "=r"((r)[2]), "=r"((r)[3]) : "r"(addr))

#define MMA16816(c, a, b0, b1)                                                     \
    asm volatile("mma.sync.aligned.m16n8k16.row.col.f32.bf16.bf16.f32 "            \
        "{%0,%1,%2,%3}, {%4,%5,%6,%7}, {%8,%9}, {%0,%1,%2,%3};"                    \
        : "+f"((c)[0]), "+f"((c)[1]), "+f"((c)[2]), "+f"((c)[3])                   \
        : "r"((a)[0]), "r"((a)[1]), "r"((a)[2]), "r"((a)[3]), "r"(b0), "r"(b1))

#define CPASYNC16(saddr, gptr)                                                     \
    asm volatile("cp.async.cg.shared.global [%0], [%1], 16;"                       \
        :: "r"(saddr), "l"(gptr))
#define CPCOMMIT() asm volatile("cp.async.commit_group;" ::: "memory")

/* ---------------- prep kernels ------------------------------------------------ */
__global__ void k_compute_w(const float* __restrict__ comp,
                            const float* __restrict__ basis, int R, int B) {
    int rd = blockIdx.x, h = threadIdx.x;
    int r = rd / HD, d = rd % HD;
    float s = 0.f;
    for (int b = 0; b < B; b++)
        s += comp[r * B + b] * basis[((size_t)b * HD + d) * HD + h];
    g_w[(size_t)rd * HD + h] = s;
}

__global__ void k_prep_b(const float* __restrict__ root, const float* __restrict__ wrel,
                         const float* __restrict__ wroot2) {
    int slot = blockIdx.x;
    const float* W = (slot < 8) ? (g_w + (size_t)slot * HD * HD)
                   : (slot == 8) ? root : (slot == 9) ? wrel : wroot2;
    unsigned short* hi = g_bimg + (size_t)(slot * 2 + 0) * BTILE;
    unsigned short* lo = g_bimg + (size_t)(slot * 2 + 1) * BTILE;
    for (int i = threadIdx.x; i < 128 * BPITCH; i += blockDim.x) {
        int n = i / BPITCH, k = i % BPITCH;
        float v = (k < HD) ? W[(size_t)k * HD + n] : 0.f;
        unsigned short h, l;
        bsplit(v, h, l);
        hi[i] = h;
        lo[i] = l;
    }
}

/* X -> split image at chunk 8 (CSR-independent) */
__global__ void __launch_bounds__(256) k_prepx(const float* __restrict__ x,
                                               int N, int mpad, size_t chStride) {
    int t = blockIdx.x * blockDim.x + threadIdx.x;
    if (t >= mpad * 32) return;
    int node = t >> 5;
    float4 v = make_float4(0.f, 0.f, 0.f, 0.f);
    if (node < N) v = ((const float4*)x)[t];
    split_store(v, g_shi, g_slo, (size_t)8 * chStride + (size_t)t * 4);
}

/* ---------------- per-(dst,rel) CSR ------------------------------------------ */
__global__ void k_hist(const int* __restrict__ ei, const int* __restrict__ et,
                       int E, int R) {
    int e = blockIdx.x * blockDim.x + threadIdx.x;
    if (e < E) atomicAdd(&g_deg2[ei[E + e] * R + et[e]], 1);
}

__global__ void __launch_bounds__(1024) k_scan_a(int n) {
    __shared__ int swarp[32];
    int b = blockIdx.x, t = threadIdx.x, i = b * 1024 + t;
    int lane = t & 31, w = t >> 5;
    int v = 0;
    if (i < n) { v = g_deg2[i]; g_deg2[i] = 0; g_cur2[i] = 0; }
    int x = v;
#pragma unroll
    for (int off = 1; off < 32; off <<= 1) {
        int y = __shfl_up_sync(0xffffffffu, x, off);
        if (lane >= off) x += y;
    }
    if (lane == 31) swarp[w] = x;
    __syncthreads();
    if (w == 0) {
        int s = swarp[lane];
#pragma unroll
        for (int off = 1; off < 32; off <<= 1) {
            int y = __shfl_up_sync(0xffffffffu, s, off);
            if (lane >= off) s += y;
        }
        swarp[lane] = s;
    }
    __syncthreads();
    int inc = x + ((w > 0) ? swarp[w - 1] : 0);
    int ex = inc - v;
    if (i < n) g_rsx[i] = ex;
    if (i == n - 1) g_rsx[n] = ex + v;
    if (t == 1023) g_bsum[b] = inc;
}

__global__ void __launch_bounds__(512) k_scan_b(int nblk) {
    __shared__ int swarp[16];
    int t = threadIdx.x, lane = t & 31, w = t >> 5;
    int v = (t < nblk) ? g_bsum[t] : 0;
    int x = v;
#pragma unroll
    for (int off = 1; off < 32; off <<= 1) {
        int y = __shfl_up_sync(0xffffffffu, x, off);
        if (lane >= off) x += y;
    }
    if (lane == 31) swarp[w] = x;
    __syncthreads();
    if (w == 0 && lane < 16) {
        int s = swarp[lane];
#pragma unroll
        for (int off = 1; off < 16; off <<= 1) {
            int y = __shfl_up_sync(0x0000ffffu, s, off);
            if (lane >= off) s += y;
        }
        swarp[lane] = s;
    }
    __syncthreads();
    if (t < nblk) g_boff[t] = x + ((w > 0) ? swarp[w - 1] : 0) - v;
}

__global__ void k_scatter(const int* __restrict__ ei, const int* __restrict__ et,
                          int E, int R) {
    int e = blockIdx.x * blockDim.x + threadIdx.x;
    if (e >= E) return;
    int seg = ei[E + e] * R + et[e];
    int pos = g_rsx[seg] + g_boff[seg >> 10] + atomicAdd(&g_cur2[seg], 1);
    g_csrc[pos] = ei[e];
}

/* ---------------- S builder (chunks 0..7) ------------------------------------- */
__global__ void __launch_bounds__(256) k_aggx(const float* __restrict__ x,
                                              int N, int mpad, size_t chStride) {
    int gt = blockIdx.x * blockDim.x + threadIdx.x;
    int node = gt >> 5, lane = gt & 31;
    if (node >= mpad) return;
    bool real = node < N;
    uint32_t bd = 0;
    if (real && lane < 9) {
        int seg = node * 8 + lane;
        bd = (uint32_t)(g_rsx[seg] + g_boff[seg >> 10]);
    }
    uint32_t a0 = __shfl_sync(0xffffffffu, bd, 0);
    uint32_t a8 = __shfl_sync(0xffffffffu, bd, 8);
    float inv = 1.f / fmaxf((float)(int)(a8 - a0), 1.f);
    size_t rowOff = (size_t)node * HD + lane * 4;

#pragma unroll
    for (int r = 0; r < 8; r++) {
        uint32_t s0 = __shfl_sync(0xffffffffu, bd, r);
        uint32_t s1 = __shfl_sync(0xffffffffu, bd, r + 1);
        float4 acc = make_float4(0.f, 0.f, 0.f, 0.f);
        uint32_t i = s0;
        for (; i + 2 <= s1; i += 2) {
            int sa = g_csrc[i], sb = g_csrc[i + 1];
            float4 va = ((const float4*)x)[(size_t)sa * 32 + lane];
            float4 vb = ((const float4*)x)[(size_t)sb * 32 + lane];
            acc.x += va.x + vb.x; acc.y += va.y + vb.y;
            acc.z += va.z + vb.z; acc.w += va.w + vb.w;
        }
        if (i < s1) {
            float4 va = ((const float4*)x)[(size_t)g_csrc[i] * 32 + lane];
            acc.x += va.x; acc.y += va.y; acc.z += va.z; acc.w += va.w;
        }
        acc.x *= inv; acc.y *= inv; acc.z *= inv; acc.w *= inv;
        split_store(acc, g_shi, g_slo, (size_t)r * chStride + rowOff);
    }
}

/* ---------------- layer-2 neighbor sum (nbr image, chunk 0) ------------------- */
__global__ void __launch_bounds__(256) k_agg2(int N, int mpad) {
    int gt = blockIdx.x * blockDim.x + threadIdx.x;
    int node = gt >> 5, lane = gt & 31;
    if (node >= mpad) return;
    uint32_t a0 = 0, a8 = 0;
    if (node < N) {
        int s = node * 8, s2 = s + 8;
        a0 = (uint32_t)(g_rsx[s] + g_boff[s >> 10]);
        a8 = (uint32_t)(g_rsx[s2] + g_boff[s2 >> 10]);
    }
    float4 acc = make_float4(0.f, 0.f, 0.f, 0.f);
    uint32_t i = a0;
    for (; i + 4 <= a8; i += 4) {
        int s0 = g_csrc[i], s1 = g_csrc[i + 1], s2 = g_csrc[i + 2], s3 = g_csrc[i + 3];
        float4 v0 = ((const float4*)g_h)[(size_t)s0 * 32 + lane];
        float4 v1 = ((const float4*)g_h)[(size_t)s1 * 32 + lane];
        float4 v2 = ((const float4*)g_h)[(size_t)s2 * 32 + lane];
        float4 v3 = ((const float4*)g_h)[(size_t)s3 * 32 + lane];
        acc.x += (v0.x + v1.x) + (v2.x + v3.x);
        acc.y += (v0.y + v1.y) + (v2.y + v3.y);
        acc.z += (v0.z + v1.z) + (v2.z + v3.z);
        acc.w += (v0.w + v1.w) + (v2.w + v3.w);
    }
    for (; i < a8; i++) {
        float4 v = ((const float4*)g_h)[(size_t)g_csrc[i] * 32 + lane];
        acc.x += v.x; acc.y += v.y; acc.z += v.z; acc.w += v.w;
    }
    split_store(acc, g_a2hi, g_a2lo, (size_t)node * HD + lane * 4);
}

/* ---------------- cp.async double-buffered split-bf16 mma.sync GEMM ----------- */
/* 2 stages x 104448 B; 1 CTA/SM; M-tile 64, N=128, K=128 per chunk             */
#define SM_AH 0
#define SM_AL 17408
#define SM_BH 34816
#define SM_BL 69632
#define STG_SZ 104448
#define SM_PIPE (2 * STG_SZ)
#define APITCHB 272

__device__ __forceinline__ void prefetch_chunk(
    uint32_t sb, const unsigned short* __restrict__ ah,
    const unsigned short* __restrict__ al,
    const unsigned short* __restrict__ bh,
    const unsigned short* __restrict__ bl, int tid)
{
#pragma unroll
    for (int i = 0; i < 4; i++) {
        int idx = tid + i * 256;
        int r = idx >> 4, c = idx & 15;
        CPASYNC16(sb + SM_AH + r * APITCHB + c * 16, ah + (size_t)r * HD + c * 8);
        CPASYNC16(sb + SM_AL + r * APITCHB + c * 16, al + (size_t)r * HD + c * 8);
    }
#pragma unroll
    for (int i = 0; i < 9; i++) {
        int idx = tid + i * 256;
        if (idx < 2176) {
            CPASYNC16(sb + SM_BH + idx * 16, bh + (size_t)idx * 8);
            CPASYNC16(sb + SM_BL + idx * 16, bl + (size_t)idx * 8);
        }
    }
}

/* WIMG: also emit split image of result; ACC: out += result (no bias) */
template<int WIMG, int ACC>
__global__ void __launch_bounds__(256) k_mma(
    const unsigned short* __restrict__ aHi, const unsigned short* __restrict__ aLo,
    size_t aStride, int nch, int bslot0, const float* __restrict__ bias,
    float* __restrict__ Cf, unsigned short* __restrict__ imgHi,
    unsigned short* __restrict__ imgLo, int M)
{
    extern __shared__ unsigned char sm[];
    uint32_t sb0 = smem_u32(sm);
    int tid = threadIdx.x, lane = tid & 31, wid = tid >> 5;
    int row0 = blockIdx.x * 64;
    int wr = wid & 1, wc = wid >> 1;
    int mrow0 = wr * 32, ncol0 = wc * 32;

    float acc[2][4][4];
#pragma unroll
    for (int a = 0; a < 2; a++)
#pragma unroll
        for (int b = 0; b < 4; b++)
#pragma unroll
            for (int c = 0; c < 4; c++) acc[a][b][c] = 0.f;

    {
        const unsigned short* ah = aHi + (size_t)row0 * HD;
        const unsigned short* al = aLo + (size_t)row0 * HD;
        const unsigned short* bh = g_bimg + (size_t)(bslot0 * 2 + 0) * BTILE;
        prefetch_chunk(sb0, ah, al, bh, bh + BTILE, tid);
        CPCOMMIT();
    }

    for (int ch = 0; ch < nch; ch++) {
        if (ch + 1 < nch) {
            const unsigned short* ah = aHi + (size_t)(ch + 1) * aStride + (size_t)row0 * HD;
            const unsigned short* al = aLo + (size_t)(ch + 1) * aStride + (size_t)row0 * HD;
            const unsigned short* bh = g_bimg + (size_t)((bslot0 + ch + 1) * 2) * BTILE;
            prefetch_chunk(sb0 + ((ch + 1) & 1) * STG_SZ, ah, al, bh, bh + BTILE, tid);
            CPCOMMIT();
            asm volatile("cp.async.wait_group 1;" ::: "memory");
        } else {
            asm volatile("cp.async.wait_group 0;" ::: "memory");
        }
        __syncthreads();

        uint32_t sbase = sb0 + (ch & 1) * STG_SZ;
#pragma unroll
        for (int ks = 0; ks < 8; ks++) {
            uint32_t koff = ks * 32 + (lane >> 4) * 16;
            uint32_t ra[2][4], rl[2][4];
#pragma unroll
            for (int mf = 0; mf < 2; mf++) {
                uint32_t arow = (uint32_t)(mrow0 + mf * 16 + (lane & 15)) * APITCHB + koff;
                LDSM4(ra[mf], sbase + SM_AH + arow);
                LDSM4(rl[mf], sbase + SM_AL + arow);
            }
#pragma unroll
            for (int nf2 = 0; nf2 < 2; nf2++) {
                uint32_t brow = (uint32_t)(ncol0 + nf2 * 16 + (lane & 15)) * APITCHB + koff;
                uint32_t bh[4], bl[4];
                LDSM4(bh, sbase + SM_BH + brow);
                LDSM4(bl, sbase + SM_BL + brow);
#pragma unroll
                for (int mf = 0; mf < 2; mf++) {
#pragma unroll
                    for (int nfr = 0; nfr < 2; nfr++) {
                        float* c = acc[mf][nf2 * 2 + nfr];
                        MMA16816(c, ra[mf], bh[nfr], bh[nfr + 2]);   /* hi*hi */
                        MMA16816(c, rl[mf], bh[nfr], bh[nfr + 2]);   /* lo*hi */
                        MMA16816(c, ra[mf], bl[nfr], bl[nfr + 2]);   /* hi*lo */
                    }
                }
            }
        }
        __syncthreads();
    }

    /* epilogue */
    int g = lane >> 2, tc = lane & 3;
#pragma unroll
    for (int mf = 0; mf < 2; mf++) {
#pragma unroll
        for (int nf = 0; nf < 4; nf++) {
            int col = ncol0 + (nf >> 1) * 16 + (nf & 1) * 8 + tc * 2;
            float bx = ACC ? 0.f : bias[col];
            float by = ACC ? 0.f : bias[col + 1];
            float* c = acc[mf][nf];
            int rowA = row0 + mrow0 + mf * 16 + g;
            int rowB = rowA + 8;
            float v0 = c[0] + bx, v1 = c[1] + by;
            float v2 = c[2] + bx, v3 = c[3] + by;
            if (rowA < M) {
                float2* cp = (float2*)(Cf + (size_t)rowA * HD + col);
                if (ACC) { float2 o = *cp; v0 += o.x; v1 += o.y; }
                *cp = make_float2(v0, v1);
            }
            if (rowB < M) {
                float2* cp = (float2*)(Cf + (size_t)rowB * HD + col);
                if (ACC) { float2 o = *cp; v2 += o.x; v3 += o.y; }
                *cp = make_float2(v2, v3);
            }
            if (WIMG) {
                unsigned short h0, l0, h1, l1;
                bsplit(v0, h0, l0); bsplit(v1, h1, l1);
                *(uint32_t*)&imgHi[(size_t)rowA * HD + col] = pack2(h0, h1);
                *(uint32_t*)&imgLo[(size_t)rowA * HD + col] = pack2(l0, l1);
                bsplit(v2, h0, l0); bsplit(v3, h1, l1);
                *(uint32_t*)&imgHi[(size_t)rowB * HD + col] = pack2(h0, h1);
                *(uint32_t*)&imgLo[(size_t)rowB * HD + col] = pack2(l0, l1);
            }
        }
    }
}

/* ---------------- host -------------------------------------------------------- */
extern "C" void kernel_launch(void* const* d_in, const int* in_sizes, int n_in,
                              void* d_out, int out_size) {
    const float* x       = (const float*)d_in[0];
    const int*   ei      = (const int*)  d_in[1];
    const int*   et      = (const int*)  d_in[3];
    const float* basis   = (const float*)d_in[4];
    const float* comp    = (const float*)d_in[5];
    const float* root    = (const float*)d_in[6];
    const float* bias1   = (const float*)d_in[7];
    const float* w_rel   = (const float*)d_in[8];
    const float* w_root2 = (const float*)d_in[9];
    const float* bias2   = (const float*)d_in[10];
    float* out = (float*)d_out;

    int N = in_sizes[0] / HD;
    int E = in_sizes[2];
    int B = in_sizes[4] / (HD * HD);
    int R = in_sizes[5] / B;
    int mpad = ((N + 127) / 128) * 128;
    int NR = N * R;
    size_t chStride = (size_t)mpad * HD;

    float* p_h;
    unsigned short *p_shi, *p_slo, *p_a2hi, *p_a2lo;
    cudaGetSymbolAddress((void**)&p_h,    g_h);
    cudaGetSymbolAddress((void**)&p_shi,  g_shi);
    cudaGetSymbolAddress((void**)&p_slo,  g_slo);
    cudaGetSymbolAddress((void**)&p_a2hi, g_a2hi);
    cudaGetSymbolAddress((void**)&p_a2lo, g_a2lo);

    /* one-time resources (created on the uncaptured correctness call) */
    static cudaStream_t s2 = nullptr;
    static cudaEvent_t evFork = nullptr, evJoin = nullptr;
    static cudaEvent_t evFork2 = nullptr, evJoin2 = nullptr;
    if (!s2) {
        cudaStreamCreateWithFlags(&s2, cudaStreamNonBlocking);
        cudaEventCreateWithFlags(&evFork,  cudaEventDisableTiming);
        cudaEventCreateWithFlags(&evJoin,  cudaEventDisableTiming);
        cudaEventCreateWithFlags(&evFork2, cudaEventDisableTiming);
        cudaEventCreateWithFlags(&evJoin2, cudaEventDisableTiming);
        cudaFuncSetAttribute(k_mma<0,0>, cudaFuncAttributeMaxDynamicSharedMemorySize, SM_PIPE);
        cudaFuncSetAttribute(k_mma<0,1>, cudaFuncAttributeMaxDynamicSharedMemorySize, SM_PIPE);
        cudaFuncSetAttribute(k_mma<1,0>, cudaFuncAttributeMaxDynamicSharedMemorySize, SM_PIPE);
    }

    int nblk = (NR + 1023) / 1024;

    /* fork 1: prep on side stream, CSR+aggx on main */
    cudaEventRecord(evFork, 0);
    cudaStreamWaitEvent(s2, evFork, 0);

    k_compute_w<<<R * HD, HD, 0, s2>>>(comp, basis, R, B);
    k_prep_b<<<11, 256, 0, s2>>>(root, w_rel, w_root2);
    k_prepx<<<(mpad * 32 + 255) / 256, 256, 0, s2>>>(x, N, mpad, chStride);

    k_hist<<<(E + 255) / 256, 256>>>(ei, et, E, R);
    k_scan_a<<<nblk, 1024>>>(NR);
    k_scan_b<<<1, 512>>>(nblk);
    k_scatter<<<(E + 255) / 256, 256>>>(ei, et, E, R);
    k_aggx<<<mpad * 32 / 256, 256>>>(x, N, mpad, chStride);

    cudaEventRecord(evJoin, s2);
    cudaStreamWaitEvent(0, evJoin, 0);

    /* layer 1: h = [S | X] @ [w;root] + bias1, emit h image (chunk 1) */
    k_mma<1,0><<<mpad / 64, 256, SM_PIPE>>>(p_shi, p_slo, chStride, R + 1, 0, bias1,
                                            p_h, p_a2hi + chStride, p_a2lo + chStride, N);

    /* fork 2: out = h @ w_root2 + bias2 on side stream; agg2 on main */
    cudaEventRecord(evFork2, 0);
    cudaStreamWaitEvent(s2, evFork2, 0);

    k_mma<0,0><<<mpad / 64, 256, SM_PIPE, s2>>>(p_a2hi + chStride, p_a2lo + chStride,
                                                chStride, 1, 10, bias2,
                                                out, nullptr, nullptr, N);

    k_agg2<<<mpad * 32 / 256, 256>>>(N, mpad);

    cudaEventRecord(evJoin2, s2);
    cudaStreamWaitEvent(0, evJoin2, 0);

    /* out += nbr @ w_rel */
    k_mma<0,1><<<mpad / 64, 256, SM_PIPE>>>(p_a2hi, p_a2lo, chStride, 1, 9, nullptr,
                                            out, nullptr, nullptr, N);
}

// round 17
// speedup vs baseline: 1.0701x; 1.0701x over previous
#include <cuda_runtime.h>
#include <cuda_bf16.h>
#include <cstdint>

#define HD 128
#define MAXN 40000
#define MAXR 8
#define MAXE 640000
#define MAXNR (MAXN * MAXR)
#define MPADC (((MAXN + 127) / 128) * 128)

/* ---------------- scratch (static device globals; no allocation) ------------- */
__device__ float g_w[MAXR * HD * HD];
__device__ float g_h[(size_t)MPADC * HD];
__device__ int   g_deg2[MAXNR];
__device__ int   g_rsx[MAXNR + 1];
__device__ int   g_cur2[MAXNR];
__device__ int   g_csrc[MAXE];
__device__ int   g_bsum[512], g_boff[512];
__device__ unsigned short g_shi[(size_t)9 * MPADC * HD];
__device__ unsigned short g_slo[(size_t)9 * MPADC * HD];
__device__ unsigned short g_a2hi[(size_t)2 * MPADC * HD];
__device__ unsigned short g_a2lo[(size_t)2 * MPADC * HD];
#define BPITCH 136
#define BTILE  (128 * BPITCH)
__device__ unsigned short g_bimg[11 * 2 * BTILE];

/* ---------------- helpers ---------------------------------------------------- */
__device__ __forceinline__ uint32_t smem_u32(const void* p) {
    uint32_t a;
    asm("{ .reg .u64 t; cvta.to.shared.u64 t, %1; cvt.u32.u64 %0, t; }" : "=r"(a) : "l"(p));
    return a;
}
__device__ __forceinline__ void bsplit(float v, unsigned short& h, unsigned short& l) {
    __nv_bfloat16 bh = __float2bfloat16(v);
    h = __bfloat16_as_ushort(bh);
    l = __bfloat16_as_ushort(__float2bfloat16(v - __bfloat162float(bh)));
}
__device__ __forceinline__ uint32_t pack2(unsigned short a, unsigned short b) {
    return (uint32_t)a | ((uint32_t)b << 16);
}
__device__ __forceinline__ void split_store(float4 v, unsigned short* hi,
                                            unsigned short* lo, size_t idx) {
    unsigned short h0, l0, h1, l1, h2, l2, h3, l3;
    bsplit(v.x, h0, l0); bsplit(v.y, h1, l1);
    bsplit(v.z, h2, l2); bsplit(v.w, h3, l3);
    *(uint2*)&hi[idx] = make_uint2(pack2(h0, h1), pack2(h2, h3));
    *(uint2*)&lo[idx] = make_uint2(pack2(l0, l1), pack2(l2, l3));
}

#define LDSM4(r, addr)                                                             \
    asm volatile("ldmatrix.sync.aligned.m8n8.x4.shared.b16 {%0,%1,%2,%3}, [%4];"   \
        : "=r"((r)[0]), "=r"((r)[1]), "=r"((r)[2]), "=r"((r)[3]) : "r"(addr))

#define MMA16816(c, a, b0, b1)                                                     \
    asm volatile("mma.sync.aligned.m16n8k16.row.col.f32.bf16.bf16.f32 "            \
        "{%0,%1,%2,%3}, {%4,%5,%6,%7}, {%8,%9}, {%0,%1,%2,%3};"                    \
        : "+f"((c)[0]), "+f"((c)[1]), "+f"((c)[2]), "+f"((c)[3])                   \
        : "r"((a)[0]), "r"((a)[1]), "r"((a)[2]), "r"((a)[3]), "r"(b0), "r"(b1))

#define CPASYNC16(saddr, gptr)                                                     \
    asm volatile("cp.async.cg.shared.global [%0], [%1], 16;"                       \
        :: "r"(saddr), "l"(gptr))
#define CPCOMMIT() asm volatile("cp.async.commit_group;" ::: "memory")

/* ---------------- prep kernels ------------------------------------------------ */
__global__ void k_compute_w(const float* __restrict__ comp,
                            const float* __restrict__ basis, int R, int B) {
    int rd = blockIdx.x, h = threadIdx.x;
    int r = rd / HD, d = rd % HD;
    float s = 0.f;
    for (int b = 0; b < B; b++)
        s += comp[r * B + b] * basis[((size_t)b * HD + d) * HD + h];
    g_w[(size_t)rd * HD + h] = s;
}

__global__ void k_prep_b(const float* __restrict__ root, const float* __restrict__ wrel,
                         const float* __restrict__ wroot2) {
    int slot = blockIdx.x;
    const float* W = (slot < 8) ? (g_w + (size_t)slot * HD * HD)
                   : (slot == 8) ? root : (slot == 9) ? wrel : wroot2;
    unsigned short* hi = g_bimg + (size_t)(slot * 2 + 0) * BTILE;
    unsigned short* lo = g_bimg + (size_t)(slot * 2 + 1) * BTILE;
    for (int i = threadIdx.x; i < 128 * BPITCH; i += blockDim.x) {
        int n = i / BPITCH, k = i % BPITCH;
        float v = (k < HD) ? W[(size_t)k * HD + n] : 0.f;
        unsigned short h, l;
        bsplit(v, h, l);
        hi[i] = h;
        lo[i] = l;
    }
}

/* X -> split image at chunk 8 (hoisted out of aggx; CSR-independent) */
__global__ void __launch_bounds__(256) k_prepx(const float* __restrict__ x,
                                               int N, int mpad, size_t chStride) {
    int t = blockIdx.x * blockDim.x + threadIdx.x;
    if (t >= mpad * 32) return;
    int node = t >> 5;
    float4 v = make_float4(0.f, 0.f, 0.f, 0.f);
    if (node < N) v = ((const float4*)x)[t];
    split_store(v, g_shi, g_slo, (size_t)8 * chStride + (size_t)t * 4);
}

/* ---------------- per-(dst,rel) CSR ------------------------------------------ */
__global__ void k_hist(const int* __restrict__ ei, const int* __restrict__ et,
                       int E, int R) {
    int e = blockIdx.x * blockDim.x + threadIdx.x;
    if (e < E) atomicAdd(&g_deg2[ei[E + e] * R + et[e]], 1);
}

__global__ void __launch_bounds__(1024) k_scan_a(int n) {
    __shared__ int swarp[32];
    int b = blockIdx.x, t = threadIdx.x, i = b * 1024 + t;
    int lane = t & 31, w = t >> 5;
    int v = 0;
    if (i < n) { v = g_deg2[i]; g_deg2[i] = 0; g_cur2[i] = 0; }
    int x = v;
#pragma unroll
    for (int off = 1; off < 32; off <<= 1) {
        int y = __shfl_up_sync(0xffffffffu, x, off);
        if (lane >= off) x += y;
    }
    if (lane == 31) swarp[w] = x;
    __syncthreads();
    if (w == 0) {
        int s = swarp[lane];
#pragma unroll
        for (int off = 1; off < 32; off <<= 1) {
            int y = __shfl_up_sync(0xffffffffu, s, off);
            if (lane >= off) s += y;
        }
        swarp[lane] = s;
    }
    __syncthreads();
    int inc = x + ((w > 0) ? swarp[w - 1] : 0);
    int ex = inc - v;
    if (i < n) g_rsx[i] = ex;
    if (i == n - 1) g_rsx[n] = ex + v;
    if (t == 1023) g_bsum[b] = inc;
}

__global__ void __launch_bounds__(512) k_scan_b(int nblk) {
    __shared__ int swarp[16];
    int t = threadIdx.x, lane = t & 31, w = t >> 5;
    int v = (t < nblk) ? g_bsum[t] : 0;
    int x = v;
#pragma unroll
    for (int off = 1; off < 32; off <<= 1) {
        int y = __shfl_up_sync(0xffffffffu, x, off);
        if (lane >= off) x += y;
    }
    if (lane == 31) swarp[w] = x;
    __syncthreads();
    if (w == 0 && lane < 16) {
        int s = swarp[lane];
#pragma unroll
        for (int off = 1; off < 16; off <<= 1) {
            int y = __shfl_up_sync(0x0000ffffu, s, off);
            if (lane >= off) s += y;
        }
        swarp[lane] = s;
    }
    __syncthreads();
    if (t < nblk) g_boff[t] = x + ((w > 0) ? swarp[w - 1] : 0) - v;
}

__global__ void k_scatter(const int* __restrict__ ei, const int* __restrict__ et,
                          int E, int R) {
    int e = blockIdx.x * blockDim.x + threadIdx.x;
    if (e >= E) return;
    int seg = ei[E + e] * R + et[e];
    int pos = g_rsx[seg] + g_boff[seg >> 10] + atomicAdd(&g_cur2[seg], 1);
    g_csrc[pos] = ei[e];
}

/* ---------------- S builder (chunks 0..7; X in k_prepx) ----------------------- */
__global__ void __launch_bounds__(256) k_aggx(const float* __restrict__ x,
                                              int N, int mpad, size_t chStride) {
    int gt = blockIdx.x * blockDim.x + threadIdx.x;
    int node = gt >> 5, lane = gt & 31;
    if (node >= mpad) return;
    bool real = node < N;
    uint32_t bd = 0;
    if (real && lane < 9) {
        int seg = node * 8 + lane;
        bd = (uint32_t)(g_rsx[seg] + g_boff[seg >> 10]);
    }
    uint32_t a0 = __shfl_sync(0xffffffffu, bd, 0);
    uint32_t a8 = __shfl_sync(0xffffffffu, bd, 8);
    float inv = 1.f / fmaxf((float)(int)(a8 - a0), 1.f);
    size_t rowOff = (size_t)node * HD + lane * 4;

#pragma unroll
    for (int r = 0; r < 8; r++) {
        uint32_t s0 = __shfl_sync(0xffffffffu, bd, r);
        uint32_t s1 = __shfl_sync(0xffffffffu, bd, r + 1);
        float4 acc = make_float4(0.f, 0.f, 0.f, 0.f);
        uint32_t i = s0;
        for (; i + 2 <= s1; i += 2) {
            int sa = g_csrc[i], sb = g_csrc[i + 1];
            float4 va = ((const float4*)x)[(size_t)sa * 32 + lane];
            float4 vb = ((const float4*)x)[(size_t)sb * 32 + lane];
            acc.x += va.x + vb.x; acc.y += va.y + vb.y;
            acc.z += va.z + vb.z; acc.w += va.w + vb.w;
        }
        if (i < s1) {
            float4 va = ((const float4*)x)[(size_t)g_csrc[i] * 32 + lane];
            acc.x += va.x; acc.y += va.y; acc.z += va.z; acc.w += va.w;
        }
        acc.x *= inv; acc.y *= inv; acc.z *= inv; acc.w *= inv;
        split_store(acc, g_shi, g_slo, (size_t)r * chStride + rowOff);
    }
}

/* ---------------- layer-2 neighbor sum --------------------------------------- */
__global__ void __launch_bounds__(256) k_agg2(int N, int mpad) {
    int gt = blockIdx.x * blockDim.x + threadIdx.x;
    int node = gt >> 5, lane = gt & 31;
    if (node >= mpad) return;
    uint32_t a0 = 0, a8 = 0;
    if (node < N) {
        int s = node * 8, s2 = s + 8;
        a0 = (uint32_t)(g_rsx[s] + g_boff[s >> 10]);
        a8 = (uint32_t)(g_rsx[s2] + g_boff[s2 >> 10]);
    }
    float4 acc = make_float4(0.f, 0.f, 0.f, 0.f);
    uint32_t i = a0;
    for (; i + 4 <= a8; i += 4) {
        int s0 = g_csrc[i], s1 = g_csrc[i + 1], s2 = g_csrc[i + 2], s3 = g_csrc[i + 3];
        float4 v0 = ((const float4*)g_h)[(size_t)s0 * 32 + lane];
        float4 v1 = ((const float4*)g_h)[(size_t)s1 * 32 + lane];
        float4 v2 = ((const float4*)g_h)[(size_t)s2 * 32 + lane];
        float4 v3 = ((const float4*)g_h)[(size_t)s3 * 32 + lane];
        acc.x += (v0.x + v1.x) + (v2.x + v3.x);
        acc.y += (v0.y + v1.y) + (v2.y + v3.y);
        acc.z += (v0.z + v1.z) + (v2.z + v3.z);
        acc.w += (v0.w + v1.w) + (v2.w + v3.w);
    }
    for (; i < a8; i++) {
        float4 v = ((const float4*)g_h)[(size_t)g_csrc[i] * 32 + lane];
        acc.x += v.x; acc.y += v.y; acc.z += v.z; acc.w += v.w;
    }
    split_store(acc, g_a2hi, g_a2lo, (size_t)node * HD + lane * 4);
}

/* ---------------- cp.async double-buffered split-bf16 mma.sync GEMM ----------- */
/* 2 stages x 104448 B; 1 CTA/SM; M-tile 64, N=128, K=128 per chunk             */
#define SM_AH 0
#define SM_AL 17408
#define SM_BH 34816
#define SM_BL 69632
#define STG_SZ 104448
#define SM_PIPE (2 * STG_SZ)
#define APITCHB 272

__device__ __forceinline__ void prefetch_chunk(
    uint32_t sb, const unsigned short* __restrict__ ah,
    const unsigned short* __restrict__ al,
    const unsigned short* __restrict__ bh,
    const unsigned short* __restrict__ bl, int tid)
{
#pragma unroll
    for (int i = 0; i < 4; i++) {
        int idx = tid + i * 256;
        int r = idx >> 4, c = idx & 15;
        CPASYNC16(sb + SM_AH + r * APITCHB + c * 16, ah + (size_t)r * HD + c * 8);
        CPASYNC16(sb + SM_AL + r * APITCHB + c * 16, al + (size_t)r * HD + c * 8);
    }
#pragma unroll
    for (int i = 0; i < 9; i++) {
        int idx = tid + i * 256;
        if (idx < 2176) {
            CPASYNC16(sb + SM_BH + idx * 16, bh + (size_t)idx * 8);
            CPASYNC16(sb + SM_BL + idx * 16, bl + (size_t)idx * 8);
        }
    }
}

template<int WIMG>
__global__ void __launch_bounds__(256) k_mma(
    const unsigned short* __restrict__ aHi, const unsigned short* __restrict__ aLo,
    size_t aStride, int nch, int bslot0, const float* __restrict__ bias,
    float* __restrict__ Cf, unsigned short* __restrict__ imgHi,
    unsigned short* __restrict__ imgLo, int M)
{
    extern __shared__ unsigned char sm[];
    uint32_t sb0 = smem_u32(sm);
    int tid = threadIdx.x, lane = tid & 31, wid = tid >> 5;
    int row0 = blockIdx.x * 64;
    int wr = wid & 1, wc = wid >> 1;
    int mrow0 = wr * 32, ncol0 = wc * 32;

    float acc[2][4][4];
#pragma unroll
    for (int a = 0; a < 2; a++)
#pragma unroll
        for (int b = 0; b < 4; b++)
#pragma unroll
            for (int c = 0; c < 4; c++) acc[a][b][c] = 0.f;

    {
        const unsigned short* ah = aHi + (size_t)row0 * HD;
        const unsigned short* al = aLo + (size_t)row0 * HD;
        const unsigned short* bh = g_bimg + (size_t)(bslot0 * 2 + 0) * BTILE;
        prefetch_chunk(sb0, ah, al, bh, bh + BTILE, tid);
        CPCOMMIT();
    }

    for (int ch = 0; ch < nch; ch++) {
        if (ch + 1 < nch) {
            const unsigned short* ah = aHi + (size_t)(ch + 1) * aStride + (size_t)row0 * HD;
            const unsigned short* al = aLo + (size_t)(ch + 1) * aStride + (size_t)row0 * HD;
            const unsigned short* bh = g_bimg + (size_t)((bslot0 + ch + 1) * 2) * BTILE;
            prefetch_chunk(sb0 + ((ch + 1) & 1) * STG_SZ, ah, al, bh, bh + BTILE, tid);
            CPCOMMIT();
            asm volatile("cp.async.wait_group 1;" ::: "memory");
        } else {
            asm volatile("cp.async.wait_group 0;" ::: "memory");
        }
        __syncthreads();

        uint32_t sbase = sb0 + (ch & 1) * STG_SZ;
#pragma unroll
        for (int ks = 0; ks < 8; ks++) {
            uint32_t koff = ks * 32 + (lane >> 4) * 16;
            uint32_t ra[2][4], rl[2][4];
#pragma unroll
            for (int mf = 0; mf < 2; mf++) {
                uint32_t arow = (uint32_t)(mrow0 + mf * 16 + (lane & 15)) * APITCHB + koff;
                LDSM4(ra[mf], sbase + SM_AH + arow);
                LDSM4(rl[mf], sbase + SM_AL + arow);
            }
#pragma unroll
            for (int nf2 = 0; nf2 < 2; nf2++) {
                uint32_t brow = (uint32_t)(ncol0 + nf2 * 16 + (lane & 15)) * APITCHB + koff;
                uint32_t bh[4], bl[4];
                LDSM4(bh, sbase + SM_BH + brow);
                LDSM4(bl, sbase + SM_BL + brow);
#pragma unroll
                for (int mf = 0; mf < 2; mf++) {
#pragma unroll
                    for (int nfr = 0; nfr < 2; nfr++) {
                        float* c = acc[mf][nf2 * 2 + nfr];
                        MMA16816(c, ra[mf], bh[nfr], bh[nfr + 2]);   /* hi*hi */
                        MMA16816(c, rl[mf], bh[nfr], bh[nfr + 2]);   /* lo*hi */
                        MMA16816(c, ra[mf], bl[nfr], bl[nfr + 2]);   /* hi*lo */
                    }
                }
            }
        }
        __syncthreads();
    }

    /* epilogue */
    int g = lane >> 2, tc = lane & 3;
#pragma unroll
    for (int mf = 0; mf < 2; mf++) {
#pragma unroll
        for (int nf = 0; nf < 4; nf++) {
            int col = ncol0 + (nf >> 1) * 16 + (nf & 1) * 8 + tc * 2;
            float bx = bias[col], by = bias[col + 1];
            float* c = acc[mf][nf];
            int rowA = row0 + mrow0 + mf * 16 + g;
            int rowB = rowA + 8;
            float v0 = c[0] + bx, v1 = c[1] + by;
            float v2 = c[2] + bx, v3 = c[3] + by;
            if (rowA < M) *(float2*)(Cf + (size_t)rowA * HD + col) = make_float2(v0, v1);
            if (rowB < M) *(float2*)(Cf + (size_t)rowB * HD + col) = make_float2(v2, v3);
            if (WIMG) {
                unsigned short h0, l0, h1, l1;
                bsplit(v0, h0, l0); bsplit(v1, h1, l1);
                *(uint32_t*)&imgHi[(size_t)rowA * HD + col] = pack2(h0, h1);
                *(uint32_t*)&imgLo[(size_t)rowA * HD + col] = pack2(l0, l1);
                bsplit(v2, h0, l0); bsplit(v3, h1, l1);
                *(uint32_t*)&imgHi[(size_t)rowB * HD + col] = pack2(h0, h1);
                *(uint32_t*)&imgLo[(size_t)rowB * HD + col] = pack2(l0, l1);
            }
        }
    }
}

/* ---------------- host -------------------------------------------------------- */
extern "C" void kernel_launch(void* const* d_in, const int* in_sizes, int n_in,
                              void* d_out, int out_size) {
    const float* x       = (const float*)d_in[0];
    const int*   ei      = (const int*)  d_in[1];
    const int*   et      = (const int*)  d_in[3];
    const float* basis   = (const float*)d_in[4];
    const float* comp    = (const float*)d_in[5];
    const float* root    = (const float*)d_in[6];
    const float* bias1   = (const float*)d_in[7];
    const float* w_rel   = (const float*)d_in[8];
    const float* w_root2 = (const float*)d_in[9];
    const float* bias2   = (const float*)d_in[10];
    float* out = (float*)d_out;

    int N = in_sizes[0] / HD;
    int E = in_sizes[2];
    int B = in_sizes[4] / (HD * HD);
    int R = in_sizes[5] / B;
    int mpad = ((N + 127) / 128) * 128;
    int NR = N * R;
    size_t chStride = (size_t)mpad * HD;

    float* p_h;
    unsigned short *p_shi, *p_slo, *p_a2hi, *p_a2lo;
    cudaGetSymbolAddress((void**)&p_h,    g_h);
    cudaGetSymbolAddress((void**)&p_shi,  g_shi);
    cudaGetSymbolAddress((void**)&p_slo,  g_slo);
    cudaGetSymbolAddress((void**)&p_a2hi, g_a2hi);
    cudaGetSymbolAddress((void**)&p_a2lo, g_a2lo);

    /* one-time resources (created on the uncaptured correctness call) */
    static cudaStream_t s2 = nullptr;
    static cudaEvent_t evFork = nullptr, evJoin = nullptr;
    if (!s2) {
        cudaStreamCreateWithFlags(&s2, cudaStreamNonBlocking);
        cudaEventCreateWithFlags(&evFork, cudaEventDisableTiming);
        cudaEventCreateWithFlags(&evJoin, cudaEventDisableTiming);
        cudaFuncSetAttribute(k_mma<0>, cudaFuncAttributeMaxDynamicSharedMemorySize, SM_PIPE);
        cudaFuncSetAttribute(k_mma<1>, cudaFuncAttributeMaxDynamicSharedMemorySize, SM_PIPE);
    }

    int nblk = (NR + 1023) / 1024;

    /* fork: prep work on side stream, CSR+aggx on main stream */
    cudaEventRecord(evFork, 0);
    cudaStreamWaitEvent(s2, evFork, 0);

    /* side stream: weights, B images, X image */
    k_compute_w<<<R * HD, HD, 0, s2>>>(comp, basis, R, B);
    k_prep_b<<<11, 256, 0, s2>>>(root, w_rel, w_root2);
    k_prepx<<<(mpad * 32 + 255) / 256, 256, 0, s2>>>(x, N, mpad, chStride);

    /* main stream: CSR build + S images */
    k_hist<<<(E + 255) / 256, 256>>>(ei, et, E, R);
    k_scan_a<<<nblk, 1024>>>(NR);
    k_scan_b<<<1, 512>>>(nblk);
    k_scatter<<<(E + 255) / 256, 256>>>(ei, et, E, R);
    k_aggx<<<mpad * 32 / 256, 256>>>(x, N, mpad, chStride);

    /* join */
    cudaEventRecord(evJoin, s2);
    cudaStreamWaitEvent(0, evJoin, 0);

    /* layer 1: h = [S | X] @ [w;root] + bias1, emit h image (chunk 1) */
    k_mma<1><<<mpad / 64, 256, SM_PIPE>>>(p_shi, p_slo, chStride, R + 1, 0, bias1,
                                          p_h, p_a2hi + chStride, p_a2lo + chStride, N);
    /* nbr -> image (chunk 0) */
    k_agg2<<<mpad * 32 / 256, 256>>>(N, mpad);
    /* layer 2: out = [nbr | h] @ [w_rel; w_root2] + bias2 */
    k_mma<0><<<mpad / 64, 256, SM_PIPE>>>(p_a2hi, p_a2lo, chStride, 2, 9, bias2,
                                          out, nullptr, nullptr, N);
}